// round 10
// baseline (speedup 1.0000x reference)
#include <cuda_runtime.h>
#include <cuda_bf16.h>
#include <math.h>
#include <stdint.h>

#define Bdim 4
#define Sdim 2048
#define Hdim 512
#define NH   8
#define HD   64
#define H3   1536

// Static scratch (allocation-guard-safe)
__device__ uint32_t g_e_hi[(size_t)Bdim * NH * Sdim * Sdim / 2];  // bf16 pairs: exp(score) hi
__device__ uint32_t g_e_lo[(size_t)Bdim * NH * Sdim * Sdim / 2];  // bf16 pairs: exp(score) lo
__device__ float g_psum[(size_t)Bdim * NH * Sdim * 16];
__device__ float g_inv[(size_t)Bdim * NH * Sdim];
__device__ __nv_bfloat16 g_q_hi[(size_t)Bdim * NH * Sdim * HD];
__device__ __nv_bfloat16 g_q_lo[(size_t)Bdim * NH * Sdim * HD];
__device__ __nv_bfloat16 g_k_hi[(size_t)Bdim * NH * Sdim * HD];
__device__ __nv_bfloat16 g_k_lo[(size_t)Bdim * NH * Sdim * HD];
__device__ __nv_bfloat16 g_v_hi[(size_t)Bdim * Sdim * Hdim];
__device__ __nv_bfloat16 g_v_lo[(size_t)Bdim * Sdim * Hdim];
__device__ __nv_bfloat16 g_x_hi[(size_t)Bdim * Sdim * Hdim];
__device__ __nv_bfloat16 g_x_lo[(size_t)Bdim * Sdim * Hdim];
__device__ __nv_bfloat16 g_wqkv_hi[(size_t)H3 * Hdim];
__device__ __nv_bfloat16 g_wqkv_lo[(size_t)H3 * Hdim];
__device__ __nv_bfloat16 g_wout_hi[(size_t)Hdim * Hdim];
__device__ __nv_bfloat16 g_wout_lo[(size_t)Hdim * Hdim];
__device__ __nv_bfloat16 g_ctx_hi[(size_t)Bdim * Sdim * Hdim];
__device__ __nv_bfloat16 g_ctx_lo[(size_t)Bdim * Sdim * Hdim];

// ---- helpers ----------------------------------------------------------------
__device__ __forceinline__ uint32_t smem_u32(const void* p) {
    uint32_t a;
    asm("{ .reg .u64 t; cvta.to.shared.u64 t, %1; cvt.u32.u64 %0, t; }" : "=r"(a) : "l"(p));
    return a;
}
__device__ __forceinline__ void ldsm_x4(uint32_t* r, uint32_t addr) {
    asm volatile("ldmatrix.sync.aligned.m8n8.x4.shared.b16 {%0,%1,%2,%3}, [%4];"
                 : "=r"(r[0]), "=r"(r[1]), "=r"(r[2]), "=r"(r[3]) : "r"(addr));
}
__device__ __forceinline__ void ldsm_x2(uint32_t* r, uint32_t addr) {
    asm volatile("ldmatrix.sync.aligned.m8n8.x2.shared.b16 {%0,%1}, [%2];"
                 : "=r"(r[0]), "=r"(r[1]) : "r"(addr));
}
__device__ __forceinline__ void ldsm_x2t(uint32_t* r, uint32_t addr) {
    asm volatile("ldmatrix.sync.aligned.m8n8.x2.trans.shared.b16 {%0,%1}, [%2];"
                 : "=r"(r[0]), "=r"(r[1]) : "r"(addr));
}
__device__ __forceinline__ void mma_bf16(float* d, const uint32_t* a, const uint32_t* b) {
    asm volatile("mma.sync.aligned.m16n8k16.row.col.f32.bf16.bf16.f32 "
                 "{%0,%1,%2,%3}, {%4,%5,%6,%7}, {%8,%9}, {%0,%1,%2,%3};"
                 : "+f"(d[0]), "+f"(d[1]), "+f"(d[2]), "+f"(d[3])
                 : "r"(a[0]), "r"(a[1]), "r"(a[2]), "r"(a[3]), "r"(b[0]), "r"(b[1]));
}
__device__ __forceinline__ uint32_t pack_bf16x2(float e0, float e1) {
    uint32_t r;  // lower half = bf16(e0), upper = bf16(e1)
    asm("cvt.rn.bf16x2.f32 %0, %2, %1;" : "=r"(r) : "f"(e0), "f"(e1));
    return r;
}
__device__ __forceinline__ void cp_async16(uint32_t saddr, const void* gptr) {
    asm volatile("cp.async.cg.shared.global [%0], [%1], 16;" :: "r"(saddr), "l"(gptr));
}
#define CP_COMMIT() asm volatile("cp.async.commit_group;")
#define CP_WAIT0()  asm volatile("cp.async.wait_group 0;")

// ---------------------------------------------------------------------------
// K0: split fp32 -> bf16 hi/lo streams
// ---------------------------------------------------------------------------
__global__ void __launch_bounds__(256) split4_kernel(
    const float* __restrict__ src, __nv_bfloat16* __restrict__ hi,
    __nv_bfloat16* __restrict__ lo, int n4)
{
    int i = blockIdx.x * 256 + threadIdx.x;
    if (i >= n4) return;
    float4 v = ((const float4*)src)[i];
    uint32_t h01 = pack_bf16x2(v.x, v.y);
    uint32_t h23 = pack_bf16x2(v.z, v.w);
    float f0 = __uint_as_float(h01 << 16), f1 = __uint_as_float(h01 & 0xffff0000u);
    float f2 = __uint_as_float(h23 << 16), f3 = __uint_as_float(h23 & 0xffff0000u);
    uint32_t l01 = pack_bf16x2(v.x - f0, v.y - f1);
    uint32_t l23 = pack_bf16x2(v.z - f2, v.w - f3);
    ((uint2*)hi)[i] = make_uint2(h01, h23);
    ((uint2*)lo)[i] = make_uint2(l01, l23);
}

// ---------------------------------------------------------------------------
// K1/K5: bf16 3-term mma.sync GEMM, K=512. Term-major MMA order.
// ---------------------------------------------------------------------------
#define GQ_SMEM (65536 + 512)

template<int MODE>
__global__ void __launch_bounds__(256, 2) gemm512_mma_kernel(
    const __nv_bfloat16* __restrict__ Ah, const __nv_bfloat16* __restrict__ Al,
    const __nv_bfloat16* __restrict__ Bh, const __nv_bfloat16* __restrict__ Bl,
    const float* __restrict__ bias, float* __restrict__ Cout, int Ncols)
{
    extern __shared__ __align__(16) char sm[];
    float* bias_s = (float*)(sm + 65536);

    const int tid = threadIdx.x, lane = tid & 31, wid = tid >> 5;
    const int m0 = blockIdx.y * 128, n0 = blockIdx.x * 128;
    const int wm = wid & 3, wn = wid >> 2;
    const uint32_t sb = smem_u32(sm);

    if (tid < 128) bias_s[tid] = bias[n0 + tid];

    float d[2][8][4];
#pragma unroll
    for (int mt = 0; mt < 2; mt++)
#pragma unroll
        for (int nt = 0; nt < 8; nt++)
#pragma unroll
            for (int e = 0; e < 4; e++) d[mt][nt][e] = 0.f;

#define GQ_CP(kc, st)                                                             \
    _Pragma("unroll") for (int i = 0; i < 2; i++) {                               \
        int idx = tid + 256 * i; int r = idx >> 2, cc = idx & 3;                  \
        uint32_t so = (uint32_t)(st) * 32768u + r * 64 +                          \
                      ((uint32_t)(cc ^ ((r >> 1) & 3)) << 4);                     \
        size_t ga = (size_t)(m0 + r) * 512 + (kc) + cc * 8;                       \
        size_t gb = (size_t)(n0 + r) * 512 + (kc) + cc * 8;                       \
        cp_async16(sb + so,         &Ah[ga]);                                     \
        cp_async16(sb + so + 8192,  &Al[ga]);                                     \
        cp_async16(sb + so + 16384, &Bh[gb]);                                     \
        cp_async16(sb + so + 24576, &Bl[gb]);                                     \
    }                                                                             \
    CP_COMMIT();

    GQ_CP(0, 0)
    CP_WAIT0();
    __syncthreads();

    for (int c = 0; c < 16; c++) {
        const int st = c & 1;
        if (c < 15) { GQ_CP((c + 1) * 32, st ^ 1) }
        const uint32_t abase = sb + st * 32768;
        const uint32_t bbase = abase + 16384;
#pragma unroll
        for (int ks = 0; ks < 2; ks++) {
            uint32_t ah[2][4], al[2][4];
#pragma unroll
            for (int mt = 0; mt < 2; mt++) {
                int row = wm * 32 + mt * 16 + (lane & 15);
                int c16 = ks * 2 + (lane >> 4);
                uint32_t adr = abase + row * 64 + ((uint32_t)(c16 ^ ((row >> 1) & 3)) << 4);
                ldsm_x4(ah[mt], adr);
                ldsm_x4(al[mt], adr + 8192);
            }
            uint32_t bhf[8][2], blf[8][2];
#pragma unroll
            for (int p = 0; p < 4; p++) {
                int i4 = lane >> 3;
                int row = wn * 64 + p * 16 + (i4 & 1) * 8 + (lane & 7);
                int c16 = ks * 2 + (i4 >> 1);
                uint32_t adr = bbase + row * 64 + ((uint32_t)(c16 ^ ((row >> 1) & 3)) << 4);
                uint32_t t[4];
                ldsm_x4(t, adr);
                bhf[2 * p][0] = t[0]; bhf[2 * p][1] = t[2];
                bhf[2 * p + 1][0] = t[1]; bhf[2 * p + 1][1] = t[3];
                ldsm_x4(t, adr + 8192);
                blf[2 * p][0] = t[0]; blf[2 * p][1] = t[2];
                blf[2 * p + 1][0] = t[1]; blf[2 * p + 1][1] = t[3];
            }
            // term-major: 16 independent accumulators between same-acc reuses
#pragma unroll
            for (int mt = 0; mt < 2; mt++)
#pragma unroll
                for (int nt = 0; nt < 8; nt++)
                    mma_bf16(d[mt][nt], ah[mt], bhf[nt]);
#pragma unroll
            for (int mt = 0; mt < 2; mt++)
#pragma unroll
                for (int nt = 0; nt < 8; nt++)
                    mma_bf16(d[mt][nt], ah[mt], blf[nt]);
#pragma unroll
            for (int mt = 0; mt < 2; mt++)
#pragma unroll
                for (int nt = 0; nt < 8; nt++)
                    mma_bf16(d[mt][nt], al[mt], bhf[nt]);
        }
        if (c < 15) { CP_WAIT0(); }
        __syncthreads();
    }

    const int g = lane >> 2, tig = lane & 3;
#pragma unroll
    for (int mt = 0; mt < 2; mt++) {
#pragma unroll
        for (int hf = 0; hf < 2; hf++) {
            int m = m0 + wm * 32 + mt * 16 + hf * 8 + g;
            if (MODE == 0) {
                int b = m >> 11, s = m & 2047;
#pragma unroll
                for (int nt = 0; nt < 8; nt++) {
                    int cl = wn * 64 + nt * 8 + tig * 2;
                    int col = n0 + cl;
                    float e0 = d[mt][nt][hf * 2 + 0] + bias_s[cl];
                    float e1 = d[mt][nt][hf * 2 + 1] + bias_s[cl + 1];
                    uint32_t h01 = pack_bf16x2(e0, e1);
                    float f0 = __uint_as_float(h01 << 16);
                    float f1 = __uint_as_float(h01 & 0xffff0000u);
                    uint32_t l01 = pack_bf16x2(e0 - f0, e1 - f1);
                    int region = col >> 9;
                    int head = (col >> 6) & 7;
                    int d0 = col & 63;
                    if (region == 0) {
                        size_t off = ((size_t)(b * NH + head) * Sdim + s) * HD + d0;
                        *(uint32_t*)&g_q_hi[off] = h01;
                        *(uint32_t*)&g_q_lo[off] = l01;
                    } else if (region == 1) {
                        size_t off = ((size_t)(b * NH + head) * Sdim + s) * HD + d0;
                        *(uint32_t*)&g_k_hi[off] = h01;
                        *(uint32_t*)&g_k_lo[off] = l01;
                    } else {
                        size_t off = ((size_t)b * Sdim + s) * Hdim + (col - 1024);
                        *(uint32_t*)&g_v_hi[off] = h01;
                        *(uint32_t*)&g_v_lo[off] = l01;
                    }
                }
            } else {
                float* crow = Cout + (size_t)m * Ncols;
#pragma unroll
                for (int nt = 0; nt < 8; nt++) {
                    int cl = wn * 64 + nt * 8 + tig * 2;
                    float2 o = {d[mt][nt][hf * 2 + 0] + bias_s[cl],
                                d[mt][nt][hf * 2 + 1] + bias_s[cl + 1]};
                    *(float2*)&crow[n0 + cl] = o;
                }
            }
        }
    }
}

// ---------------------------------------------------------------------------
// K2: scores via mma.sync bf16 (3-term, term-major). Epilogue: e = exp(s),
// write bf16 hi/lo planes + per-CTA partial row sums.
// ---------------------------------------------------------------------------
#define SQS 72
#define SC_ARR (128 * SQS)
#define SC_SMEM (4 * SC_ARR * 2 + 128 * 3 * 4 * 2 + 128 * 4 + 128 * 2 * 4)

__global__ void __launch_bounds__(256, 2) scores_mma_kernel(
    const float* __restrict__ pos, const int* __restrict__ mask)
{
    extern __shared__ __align__(16) char sm[];
    __nv_bfloat16* Qh = (__nv_bfloat16*)sm;
    float* Pq = (float*)(sm + 4 * SC_ARR * 2);
    float* Pk = Pq + 128 * 3;
    int*   Mk = (int*)(Pk + 128 * 3);
    float* spart = (float*)(Mk + 128);

    const int tid = threadIdx.x, lane = tid & 31, wid = tid >> 5;
    const int bh = blockIdx.z, b = bh >> 3;
    const int q0 = blockIdx.y * 128, k0 = blockIdx.x * 128;
    const int kt = blockIdx.x;

    const __nv_bfloat16* sQh = g_q_hi + ((size_t)bh * Sdim + q0) * HD;
    const __nv_bfloat16* sQl = g_q_lo + ((size_t)bh * Sdim + q0) * HD;
    const __nv_bfloat16* sKh = g_k_hi + ((size_t)bh * Sdim + k0) * HD;
    const __nv_bfloat16* sKl = g_k_lo + ((size_t)bh * Sdim + k0) * HD;

    const uint32_t qb = smem_u32(Qh);
#pragma unroll
    for (int i = 0; i < 4; i++) {
        int idx = tid + 256 * i;
        int r = idx >> 3, c = idx & 7;
        uint32_t so = (r * SQS + c * 8) * 2;
        size_t go = (size_t)r * HD + c * 8;
        cp_async16(qb + so,                  &sQh[go]);
        cp_async16(qb + so + SC_ARR * 2,     &sQl[go]);
        cp_async16(qb + so + 2 * SC_ARR * 2, &sKh[go]);
        cp_async16(qb + so + 3 * SC_ARR * 2, &sKl[go]);
    }
    CP_COMMIT();

    if (tid < 128) {
        Pq[tid * 3 + 0] = pos[(size_t)(b * Sdim + q0 + tid) * 3 + 0];
        Pq[tid * 3 + 1] = pos[(size_t)(b * Sdim + q0 + tid) * 3 + 1];
        Pq[tid * 3 + 2] = pos[(size_t)(b * Sdim + q0 + tid) * 3 + 2];
    } else {
        int t2 = tid - 128;
        Pk[t2 * 3 + 0] = pos[(size_t)(b * Sdim + k0 + t2) * 3 + 0];
        Pk[t2 * 3 + 1] = pos[(size_t)(b * Sdim + k0 + t2) * 3 + 1];
        Pk[t2 * 3 + 2] = pos[(size_t)(b * Sdim + k0 + t2) * 3 + 2];
        Mk[t2]         = mask[b * Sdim + k0 + t2];
    }
    CP_WAIT0();
    __syncthreads();

    const int wm = wid & 3, wn = wid >> 2;
    const uint32_t kb = qb + 2 * SC_ARR * 2;
    const uint32_t LOFF = SC_ARR * 2;

    float d[2][8][4];
#pragma unroll
    for (int mt = 0; mt < 2; mt++)
#pragma unroll
        for (int nt = 0; nt < 8; nt++)
#pragma unroll
            for (int e = 0; e < 4; e++) d[mt][nt][e] = 0.f;

#pragma unroll
    for (int ks = 0; ks < 4; ks++) {
        uint32_t ah[2][4], al[2][4];
#pragma unroll
        for (int mt = 0; mt < 2; mt++) {
            int row = wm * 32 + mt * 16 + (lane & 15);
            int col = ks * 16 + (lane >> 4) * 8;
            uint32_t adr = qb + (row * SQS + col) * 2;
            ldsm_x4(ah[mt], adr);
            ldsm_x4(al[mt], adr + LOFF);
        }
        uint32_t bhf[8][2], blf[8][2];
#pragma unroll
        for (int nt = 0; nt < 8; nt++) {
            int row = wn * 64 + nt * 8 + (lane & 7);
            int col = ks * 16 + ((lane >> 3) & 1) * 8;
            uint32_t adr = kb + (row * SQS + col) * 2;
            ldsm_x2(bhf[nt], adr);
            ldsm_x2(blf[nt], adr + LOFF);
        }
        // term-major
#pragma unroll
        for (int mt = 0; mt < 2; mt++)
#pragma unroll
            for (int nt = 0; nt < 8; nt++)
                mma_bf16(d[mt][nt], ah[mt], bhf[nt]);
#pragma unroll
        for (int mt = 0; mt < 2; mt++)
#pragma unroll
            for (int nt = 0; nt < 8; nt++)
                mma_bf16(d[mt][nt], ah[mt], blf[nt]);
#pragma unroll
        for (int mt = 0; mt < 2; mt++)
#pragma unroll
            for (int nt = 0; nt < 8; nt++)
                mma_bf16(d[mt][nt], al[mt], bhf[nt]);
    }

    const int g = lane >> 2, tig = lane & 3;
#pragma unroll
    for (int mt = 0; mt < 2; mt++) {
#pragma unroll
        for (int hf = 0; hf < 2; hf++) {
            int lr = wm * 32 + mt * 16 + hf * 8 + g;
            float px = Pq[lr * 3 + 0], py = Pq[lr * 3 + 1], pz = Pq[lr * 3 + 2];
            uint32_t* hrow = g_e_hi + ((size_t)bh * Sdim + q0 + lr) * (Sdim / 2) + (k0 >> 1);
            uint32_t* lrow = g_e_lo + ((size_t)bh * Sdim + q0 + lr) * (Sdim / 2) + (k0 >> 1);
            float rsum = 0.f;
#pragma unroll
            for (int nt = 0; nt < 8; nt++) {
                int lc = wn * 64 + nt * 8 + tig * 2;
                float v0 = d[mt][nt][hf * 2 + 0];
                float v1 = d[mt][nt][hf * 2 + 1];
                float dx0 = px - Pk[lc * 3 + 0], dy0 = py - Pk[lc * 3 + 1], dz0 = pz - Pk[lc * 3 + 2];
                float dx1 = px - Pk[lc * 3 + 3], dy1 = py - Pk[lc * 3 + 4], dz1 = pz - Pk[lc * 3 + 5];
                float s0 = 0.125f * (v0 - (dx0 * dx0 + dy0 * dy0 + dz0 * dz0));
                float s1 = 0.125f * (v1 - (dx1 * dx1 + dy1 * dy1 + dz1 * dz1));
                float e0 = (Mk[lc] == 0)     ? 0.f : __expf(s0);
                float e1 = (Mk[lc + 1] == 0) ? 0.f : __expf(s1);
                rsum += e0 + e1;
                uint32_t h01 = pack_bf16x2(e0, e1);
                float f0 = __uint_as_float(h01 << 16);
                float f1 = __uint_as_float(h01 & 0xffff0000u);
                uint32_t l01 = pack_bf16x2(e0 - f0, e1 - f1);
                hrow[lc >> 1] = h01;
                lrow[lc >> 1] = l01;
            }
            rsum += __shfl_xor_sync(0xffffffffu, rsum, 1);
            rsum += __shfl_xor_sync(0xffffffffu, rsum, 2);
            if (tig == 0) spart[lr * 2 + wn] = rsum;
        }
    }
    __syncthreads();
    if (tid < 128) {
        float ps = spart[tid * 2] + spart[tid * 2 + 1];
        g_psum[((size_t)bh * Sdim + q0 + tid) * 16 + kt] = ps;
    }
}

// ---------------------------------------------------------------------------
// K2b: inv = 1 / sum(16 partials)
// ---------------------------------------------------------------------------
__global__ void __launch_bounds__(256) rowsum_inv_kernel()
{
    int idx = blockIdx.x * 256 + threadIdx.x;
    const float* p = g_psum + (size_t)idx * 16;
    float s = 0.f;
#pragma unroll
    for (int i = 0; i < 16; i++) s += p[i];
    g_inv[idx] = 1.0f / s;
}

// ---------------------------------------------------------------------------
// K3: head-mean (pure stream) from hi/lo planes
// ---------------------------------------------------------------------------
__global__ void __launch_bounds__(256) mean_kernel(float* __restrict__ mean_out)
{
    const int bq = blockIdx.x;
    const int b = bq >> 11, q = bq & 2047;
    const int tid = threadIdx.x;
    const int pbase = tid * 4;   // uint32-pair index; elements tid*8..tid*8+7

    __shared__ float inv_s[8];
    if (tid < 8) inv_s[tid] = g_inv[(size_t)(b * NH + tid) * Sdim + q];
    __syncthreads();

    float macc[8];
#pragma unroll
    for (int j = 0; j < 8; j++) macc[j] = 0.f;

#pragma unroll
    for (int h = 0; h < NH; h++) {
        size_t rb = ((size_t)((b * NH + h) * Sdim + q)) * (Sdim / 2);
        uint4 vh = *(const uint4*)&g_e_hi[rb + pbase];
        uint4 vl = *(const uint4*)&g_e_lo[rb + pbase];
        uint32_t hw[4] = {vh.x, vh.y, vh.z, vh.w};
        uint32_t lw[4] = {vl.x, vl.y, vl.z, vl.w};
        float invh = inv_s[h];
#pragma unroll
        for (int m = 0; m < 4; m++) {
            float e0 = __uint_as_float(hw[m] << 16) + __uint_as_float(lw[m] << 16);
            float e1 = __uint_as_float(hw[m] & 0xffff0000u) + __uint_as_float(lw[m] & 0xffff0000u);
            macc[2 * m]     = fmaf(e0, invh, macc[2 * m]);
            macc[2 * m + 1] = fmaf(e1, invh, macc[2 * m + 1]);
        }
    }

    float* mrow = mean_out + ((size_t)(b * Sdim + q)) * Sdim + tid * 8;
    float4 m0 = {macc[0] * 0.125f, macc[1] * 0.125f, macc[2] * 0.125f, macc[3] * 0.125f};
    float4 m1 = {macc[4] * 0.125f, macc[5] * 0.125f, macc[6] * 0.125f, macc[7] * 0.125f};
    *(float4*)&mrow[0] = m0;
    *(float4*)&mrow[4] = m1;
}

// ---------------------------------------------------------------------------
// K4: pv via mma.sync bf16 (3-term, term-major). All operands via cp.async,
// single __syncthreads per chunk. ctx written pre-split bf16 hi/lo.
// ---------------------------------------------------------------------------
#define PV_STAGE_B 49152
#define PV_WL_OFF  16384
#define PV_VH_OFF  32768
#define PV_VL_OFF  40960
#define PV_BASE    1024
#define PV_SMEM_B  (PV_BASE + 2 * PV_STAGE_B)

__global__ void __launch_bounds__(256, 2) pv_mma_kernel()
{
    extern __shared__ __align__(16) char sm[];
    float* inv_s = (float*)sm;

    const int tid = threadIdx.x, lane = tid & 31, wid = tid >> 5;
    const int bh = blockIdx.y, b = bh >> 3, h = bh & 7;
    const int q0 = blockIdx.x * 128;

    const uint32_t* Eh = g_e_hi + ((size_t)bh * Sdim + q0) * (Sdim / 2);
    const uint32_t* El = g_e_lo + ((size_t)bh * Sdim + q0) * (Sdim / 2);
    const __nv_bfloat16* Vh_src = g_v_hi + (size_t)b * Sdim * Hdim + h * HD;
    const __nv_bfloat16* Vl_src = g_v_lo + (size_t)b * Sdim * Hdim + h * HD;

    const uint32_t sb = smem_u32(sm);
    const int wm = wid & 3, wn = wid >> 2;

    if (tid < 128)
        inv_s[tid] = g_inv[(size_t)bh * Sdim + q0 + tid];

    float d[2][4][4];
#pragma unroll
    for (int mt = 0; mt < 2; mt++)
#pragma unroll
        for (int nt = 0; nt < 4; nt++)
#pragma unroll
            for (int e = 0; e < 4; e++) d[mt][nt][e] = 0.f;

    // W chunk: 128 q-rows x 64 k (bf16) per plane; 16B units: r 0..127, cc 0..7
#define PV_CPW(kc, st)                                                            \
    _Pragma("unroll") for (int i = 0; i < 4; i++) {                               \
        int idx = tid + 256 * i; int r = idx >> 3, cc = idx & 7;                  \
        uint32_t soff = r * 128 + ((cc * 16) ^ ((r & 7) * 16));                   \
        uint32_t base = sb + PV_BASE + (st) * PV_STAGE_B;                         \
        size_t go = (size_t)r * (Sdim / 2) + ((kc) >> 1) + cc * 4;                \
        cp_async16(base + soff,             &Eh[go]);                             \
        cp_async16(base + PV_WL_OFF + soff, &El[go]);                             \
    }

    // V chunk: 64 k-rows x 64 d (bf16) per plane
#define PV_CPV(kc, st)                                                            \
    _Pragma("unroll") for (int i = 0; i < 2; i++) {                               \
        int idx = tid + 256 * i; int kk = idx >> 3, c8 = idx & 7;                 \
        uint32_t soff = kk * 128 + ((c8 * 16) ^ ((kk & 7) * 16));                 \
        uint32_t base = sb + PV_BASE + (st) * PV_STAGE_B;                         \
        cp_async16(base + PV_VH_OFF + soff, &Vh_src[(size_t)((kc) + kk) * Hdim + c8 * 8]); \
        cp_async16(base + PV_VL_OFF + soff, &Vl_src[(size_t)((kc) + kk) * Hdim + c8 * 8]); \
    }

    PV_CPW(0, 0)
    PV_CPV(0, 0)
    CP_COMMIT();
    CP_WAIT0();
    __syncthreads();

    for (int c = 0; c < 32; c++) {
        const int st = c & 1;
        if (c < 31) {
            PV_CPW((c + 1) * 64, st ^ 1)
            PV_CPV((c + 1) * 64, st ^ 1)
            CP_COMMIT();
        }
        {
            const uint32_t wbase = sb + PV_BASE + st * PV_STAGE_B;
            const uint32_t vbase = wbase + PV_VH_OFF;
#pragma unroll
            for (int ks = 0; ks < 4; ks++) {
                uint32_t ah[2][4], al[2][4];
#pragma unroll
                for (int mt = 0; mt < 2; mt++) {
                    int row = wm * 32 + mt * 16 + (lane & 15);
                    uint32_t colb = (ks * 16 + (lane >> 4) * 8) * 2;
                    uint32_t adr = wbase + row * 128 + (colb ^ ((row & 7) * 16));
                    ldsm_x4(ah[mt], adr);
                    ldsm_x4(al[mt], adr + PV_WL_OFF);
                }
                uint32_t bhf[4][2], blf[4][2];
#pragma unroll
                for (int nt = 0; nt < 4; nt++) {
                    int rowk = ks * 16 + (lane & 15);
                    uint32_t colb = (wn * 32 + nt * 8) * 2;
                    uint32_t adr = vbase + rowk * 128 + (colb ^ ((rowk & 7) * 16));
                    ldsm_x2t(bhf[nt], adr);
                    ldsm_x2t(blf[nt], adr + (PV_VL_OFF - PV_VH_OFF));
                }
                // term-major
#pragma unroll
                for (int mt = 0; mt < 2; mt++)
#pragma unroll
                    for (int nt = 0; nt < 4; nt++)
                        mma_bf16(d[mt][nt], ah[mt], bhf[nt]);
#pragma unroll
                for (int mt = 0; mt < 2; mt++)
#pragma unroll
                    for (int nt = 0; nt < 4; nt++)
                        mma_bf16(d[mt][nt], ah[mt], blf[nt]);
#pragma unroll
                for (int mt = 0; mt < 2; mt++)
#pragma unroll
                    for (int nt = 0; nt < 4; nt++)
                        mma_bf16(d[mt][nt], al[mt], bhf[nt]);
            }
        }
        if (c < 31) { CP_WAIT0(); }
        __syncthreads();
    }

    const int g = lane >> 2, tig = lane & 3;
#pragma unroll
    for (int mt = 0; mt < 2; mt++)
#pragma unroll
        for (int nt = 0; nt < 4; nt++)
#pragma unroll
            for (int hf = 0; hf < 2; hf++) {
                int lr = wm * 32 + mt * 16 + g + hf * 8;
                float inv = inv_s[lr];
                int m = q0 + lr;
                int col = h * HD + wn * 32 + nt * 8 + tig * 2;
                float e0 = d[mt][nt][hf * 2 + 0] * inv;
                float e1 = d[mt][nt][hf * 2 + 1] * inv;
                uint32_t h01 = pack_bf16x2(e0, e1);
                float f0 = __uint_as_float(h01 << 16);
                float f1 = __uint_as_float(h01 & 0xffff0000u);
                uint32_t l01 = pack_bf16x2(e0 - f0, e1 - f1);
                size_t off = (size_t)(b * Sdim + m) * Hdim + col;
                *(uint32_t*)&g_ctx_hi[off] = h01;
                *(uint32_t*)&g_ctx_lo[off] = l01;
            }
}

// ---------------------------------------------------------------------------
extern "C" void kernel_launch(void* const* d_in, const int* in_sizes, int n_in,
                              void* d_out, int out_size)
{
    const float* x     = (const float*)d_in[0];
    const float* pos   = (const float*)d_in[1];
    const int*   mask  = (const int*)d_in[2];
    const float* w_qkv = (const float*)d_in[3];
    const float* b_qkv = (const float*)d_in[4];
    const float* w_out = (const float*)d_in[5];
    const float* b_out = (const float*)d_in[6];

    float* out_proj = (float*)d_out;
    float* mean_out = out_proj + (size_t)Bdim * Sdim * Hdim;

    __nv_bfloat16 *p_xh, *p_xl, *p_wqh, *p_wql, *p_woh, *p_wol, *p_ch, *p_cl;
    cudaGetSymbolAddress((void**)&p_xh, g_x_hi);
    cudaGetSymbolAddress((void**)&p_xl, g_x_lo);
    cudaGetSymbolAddress((void**)&p_wqh, g_wqkv_hi);
    cudaGetSymbolAddress((void**)&p_wql, g_wqkv_lo);
    cudaGetSymbolAddress((void**)&p_woh, g_wout_hi);
    cudaGetSymbolAddress((void**)&p_wol, g_wout_lo);
    cudaGetSymbolAddress((void**)&p_ch, g_ctx_hi);
    cudaGetSymbolAddress((void**)&p_cl, g_ctx_lo);

    static cudaStream_t s_side = nullptr;
    static cudaEvent_t ev_fork = nullptr, ev_join = nullptr;
    if (!s_side) {
        cudaStreamCreateWithFlags(&s_side, cudaStreamNonBlocking);
        cudaEventCreateWithFlags(&ev_fork, cudaEventDisableTiming);
        cudaEventCreateWithFlags(&ev_join, cudaEventDisableTiming);
        cudaFuncSetAttribute(gemm512_mma_kernel<0>, cudaFuncAttributeMaxDynamicSharedMemorySize, GQ_SMEM);
        cudaFuncSetAttribute(gemm512_mma_kernel<1>, cudaFuncAttributeMaxDynamicSharedMemorySize, GQ_SMEM);
        cudaFuncSetAttribute(scores_mma_kernel, cudaFuncAttributeMaxDynamicSharedMemorySize, SC_SMEM);
        cudaFuncSetAttribute(pv_mma_kernel, cudaFuncAttributeMaxDynamicSharedMemorySize, PV_SMEM_B);
    }

    // K0: pre-split fp32 inputs to bf16 hi/lo
    split4_kernel<<<(Bdim * Sdim * Hdim / 4 + 255) / 256, 256>>>(x, p_xh, p_xl, Bdim * Sdim * Hdim / 4);
    split4_kernel<<<(H3 * Hdim / 4 + 255) / 256, 256>>>(w_qkv, p_wqh, p_wql, H3 * Hdim / 4);
    split4_kernel<<<(Hdim * Hdim / 4 + 255) / 256, 256>>>(w_out, p_woh, p_wol, Hdim * Hdim / 4);

    // K1: QKV projection (tensor) + split scatter
    {
        dim3 grid(H3 / 128, (Bdim * Sdim) / 128);
        gemm512_mma_kernel<0><<<grid, 256, GQ_SMEM>>>(p_xh, p_xl, p_wqh, p_wql, b_qkv, nullptr, H3);
    }
    // K2: scores -> exp hi/lo planes + partial sums
    {
        dim3 grid(Sdim / 128, Sdim / 128, Bdim * NH);
        scores_mma_kernel<<<grid, 256, SC_SMEM>>>(pos, mask);
    }
    // K2b: row inverse sums
    rowsum_inv_kernel<<<(Bdim * NH * Sdim) / 256, 256>>>();

    // fork: mean (side stream) overlaps pv (main stream)
    cudaEventRecord(ev_fork, 0);
    cudaStreamWaitEvent(s_side, ev_fork, 0);
    mean_kernel<<<Bdim * Sdim, 256, 0, s_side>>>(mean_out);
    cudaEventRecord(ev_join, s_side);

    // K4: ctx = inv * (e @ V) (tensor)
    {
        dim3 grid(Sdim / 128, Bdim * NH);
        pv_mma_kernel<<<grid, 256, PV_SMEM_B>>>();
    }
    // K5: output projection (tensor)
    {
        dim3 grid(Hdim / 128, (Bdim * Sdim) / 128);
        gemm512_mma_kernel<1><<<grid, 256, GQ_SMEM>>>(p_ch, p_cl, p_woh, p_wol, b_out, out_proj, Hdim);
    }
    // join: mean must complete within the captured graph
    cudaStreamWaitEvent(0, ev_join, 0);
}

// round 11
// speedup vs baseline: 1.0981x; 1.0981x over previous
#include <cuda_runtime.h>
#include <cuda_bf16.h>
#include <math.h>
#include <stdint.h>

#define Bdim 4
#define Sdim 2048
#define Hdim 512
#define NH   8
#define HD   64
#define H3   1536

// Static scratch (allocation-guard-safe)
__device__ uint32_t g_e_hi[(size_t)Bdim * NH * Sdim * Sdim / 2];  // bf16 pairs: exp(score) hi
__device__ uint32_t g_e_lo[(size_t)Bdim * NH * Sdim * Sdim / 2];  // bf16 pairs: exp(score) lo
__device__ float g_psum[(size_t)Bdim * NH * Sdim * 16];
__device__ float g_inv[(size_t)Bdim * NH * Sdim];
__device__ __nv_bfloat16 g_q_hi[(size_t)Bdim * NH * Sdim * HD];
__device__ __nv_bfloat16 g_q_lo[(size_t)Bdim * NH * Sdim * HD];
__device__ __nv_bfloat16 g_k_hi[(size_t)Bdim * NH * Sdim * HD];
__device__ __nv_bfloat16 g_k_lo[(size_t)Bdim * NH * Sdim * HD];
__device__ __nv_bfloat16 g_v_hi[(size_t)Bdim * Sdim * Hdim];
__device__ __nv_bfloat16 g_v_lo[(size_t)Bdim * Sdim * Hdim];
__device__ __nv_bfloat16 g_x_hi[(size_t)Bdim * Sdim * Hdim];
__device__ __nv_bfloat16 g_x_lo[(size_t)Bdim * Sdim * Hdim];
__device__ __nv_bfloat16 g_wqkv_hi[(size_t)H3 * Hdim];
__device__ __nv_bfloat16 g_wqkv_lo[(size_t)H3 * Hdim];
__device__ __nv_bfloat16 g_wout_hi[(size_t)Hdim * Hdim];
__device__ __nv_bfloat16 g_wout_lo[(size_t)Hdim * Hdim];
__device__ __nv_bfloat16 g_ctx_hi[(size_t)Bdim * Sdim * Hdim];
__device__ __nv_bfloat16 g_ctx_lo[(size_t)Bdim * Sdim * Hdim];

// ---- helpers ----------------------------------------------------------------
__device__ __forceinline__ uint32_t smem_u32(const void* p) {
    uint32_t a;
    asm("{ .reg .u64 t; cvta.to.shared.u64 t, %1; cvt.u32.u64 %0, t; }" : "=r"(a) : "l"(p));
    return a;
}
__device__ __forceinline__ void ldsm_x4(uint32_t* r, uint32_t addr) {
    asm volatile("ldmatrix.sync.aligned.m8n8.x4.shared.b16 {%0,%1,%2,%3}, [%4];"
                 : "=r"(r[0]), "=r"(r[1]), "=r"(r[2]), "=r"(r[3]) : "r"(addr));
}
__device__ __forceinline__ void ldsm_x2(uint32_t* r, uint32_t addr) {
    asm volatile("ldmatrix.sync.aligned.m8n8.x2.shared.b16 {%0,%1}, [%2];"
                 : "=r"(r[0]), "=r"(r[1]) : "r"(addr));
}
__device__ __forceinline__ void ldsm_x2t(uint32_t* r, uint32_t addr) {
    asm volatile("ldmatrix.sync.aligned.m8n8.x2.trans.shared.b16 {%0,%1}, [%2];"
                 : "=r"(r[0]), "=r"(r[1]) : "r"(addr));
}
__device__ __forceinline__ void mma_bf16(float* d, const uint32_t* a, const uint32_t* b) {
    asm volatile("mma.sync.aligned.m16n8k16.row.col.f32.bf16.bf16.f32 "
                 "{%0,%1,%2,%3}, {%4,%5,%6,%7}, {%8,%9}, {%0,%1,%2,%3};"
                 : "+f"(d[0]), "+f"(d[1]), "+f"(d[2]), "+f"(d[3])
                 : "r"(a[0]), "r"(a[1]), "r"(a[2]), "r"(a[3]), "r"(b[0]), "r"(b[1]));
}
__device__ __forceinline__ uint32_t pack_bf16x2(float e0, float e1) {
    uint32_t r;  // lower half = bf16(e0), upper = bf16(e1)
    asm("cvt.rn.bf16x2.f32 %0, %2, %1;" : "=r"(r) : "f"(e0), "f"(e1));
    return r;
}
__device__ __forceinline__ void cp_async16(uint32_t saddr, const void* gptr) {
    asm volatile("cp.async.cg.shared.global [%0], [%1], 16;" :: "r"(saddr), "l"(gptr));
}
#define CP_COMMIT() asm volatile("cp.async.commit_group;")
#define CP_WAIT0()  asm volatile("cp.async.wait_group 0;")

// ---------------------------------------------------------------------------
// K0: split fp32 -> bf16 hi/lo streams
// ---------------------------------------------------------------------------
__global__ void __launch_bounds__(256) split4_kernel(
    const float* __restrict__ src, __nv_bfloat16* __restrict__ hi,
    __nv_bfloat16* __restrict__ lo, int n4)
{
    int i = blockIdx.x * 256 + threadIdx.x;
    if (i >= n4) return;
    float4 v = ((const float4*)src)[i];
    uint32_t h01 = pack_bf16x2(v.x, v.y);
    uint32_t h23 = pack_bf16x2(v.z, v.w);
    float f0 = __uint_as_float(h01 << 16), f1 = __uint_as_float(h01 & 0xffff0000u);
    float f2 = __uint_as_float(h23 << 16), f3 = __uint_as_float(h23 & 0xffff0000u);
    uint32_t l01 = pack_bf16x2(v.x - f0, v.y - f1);
    uint32_t l23 = pack_bf16x2(v.z - f2, v.w - f3);
    ((uint2*)hi)[i] = make_uint2(h01, h23);
    ((uint2*)lo)[i] = make_uint2(l01, l23);
}

// ---------------------------------------------------------------------------
// K1/K5: bf16 3-term mma.sync GEMM, K=512.
// ---------------------------------------------------------------------------
#define GQ_SMEM (65536 + 512)

template<int MODE>
__global__ void __launch_bounds__(256, 2) gemm512_mma_kernel(
    const __nv_bfloat16* __restrict__ Ah, const __nv_bfloat16* __restrict__ Al,
    const __nv_bfloat16* __restrict__ Bh, const __nv_bfloat16* __restrict__ Bl,
    const float* __restrict__ bias, float* __restrict__ Cout, int Ncols)
{
    extern __shared__ __align__(16) char sm[];
    float* bias_s = (float*)(sm + 65536);

    const int tid = threadIdx.x, lane = tid & 31, wid = tid >> 5;
    const int m0 = blockIdx.y * 128, n0 = blockIdx.x * 128;
    const int wm = wid & 3, wn = wid >> 2;
    const uint32_t sb = smem_u32(sm);

    if (tid < 128) bias_s[tid] = bias[n0 + tid];

    float d[2][8][4];
#pragma unroll
    for (int mt = 0; mt < 2; mt++)
#pragma unroll
        for (int nt = 0; nt < 8; nt++)
#pragma unroll
            for (int e = 0; e < 4; e++) d[mt][nt][e] = 0.f;

#define GQ_CP(kc, st)                                                             \
    _Pragma("unroll") for (int i = 0; i < 2; i++) {                               \
        int idx = tid + 256 * i; int r = idx >> 2, cc = idx & 3;                  \
        uint32_t so = (uint32_t)(st) * 32768u + r * 64 +                          \
                      ((uint32_t)(cc ^ ((r >> 1) & 3)) << 4);                     \
        size_t ga = (size_t)(m0 + r) * 512 + (kc) + cc * 8;                       \
        size_t gb = (size_t)(n0 + r) * 512 + (kc) + cc * 8;                       \
        cp_async16(sb + so,         &Ah[ga]);                                     \
        cp_async16(sb + so + 8192,  &Al[ga]);                                     \
        cp_async16(sb + so + 16384, &Bh[gb]);                                     \
        cp_async16(sb + so + 24576, &Bl[gb]);                                     \
    }                                                                             \
    CP_COMMIT();

    GQ_CP(0, 0)
    CP_WAIT0();
    __syncthreads();

    for (int c = 0; c < 16; c++) {
        const int st = c & 1;
        if (c < 15) { GQ_CP((c + 1) * 32, st ^ 1) }
        const uint32_t abase = sb + st * 32768;
        const uint32_t bbase = abase + 16384;
#pragma unroll
        for (int ks = 0; ks < 2; ks++) {
            uint32_t ah[2][4], al[2][4];
#pragma unroll
            for (int mt = 0; mt < 2; mt++) {
                int row = wm * 32 + mt * 16 + (lane & 15);
                int c16 = ks * 2 + (lane >> 4);
                uint32_t adr = abase + row * 64 + ((uint32_t)(c16 ^ ((row >> 1) & 3)) << 4);
                ldsm_x4(ah[mt], adr);
                ldsm_x4(al[mt], adr + 8192);
            }
            uint32_t bhf[8][2], blf[8][2];
#pragma unroll
            for (int p = 0; p < 4; p++) {
                int i4 = lane >> 3;
                int row = wn * 64 + p * 16 + (i4 & 1) * 8 + (lane & 7);
                int c16 = ks * 2 + (i4 >> 1);
                uint32_t adr = bbase + row * 64 + ((uint32_t)(c16 ^ ((row >> 1) & 3)) << 4);
                uint32_t t[4];
                ldsm_x4(t, adr);
                bhf[2 * p][0] = t[0]; bhf[2 * p][1] = t[2];
                bhf[2 * p + 1][0] = t[1]; bhf[2 * p + 1][1] = t[3];
                ldsm_x4(t, adr + 8192);
                blf[2 * p][0] = t[0]; blf[2 * p][1] = t[2];
                blf[2 * p + 1][0] = t[1]; blf[2 * p + 1][1] = t[3];
            }
#pragma unroll
            for (int mt = 0; mt < 2; mt++)
#pragma unroll
                for (int nt = 0; nt < 8; nt++)
                    mma_bf16(d[mt][nt], ah[mt], bhf[nt]);
#pragma unroll
            for (int mt = 0; mt < 2; mt++)
#pragma unroll
                for (int nt = 0; nt < 8; nt++)
                    mma_bf16(d[mt][nt], ah[mt], blf[nt]);
#pragma unroll
            for (int mt = 0; mt < 2; mt++)
#pragma unroll
                for (int nt = 0; nt < 8; nt++)
                    mma_bf16(d[mt][nt], al[mt], bhf[nt]);
        }
        if (c < 15) { CP_WAIT0(); }
        __syncthreads();
    }

    const int g = lane >> 2, tig = lane & 3;
#pragma unroll
    for (int mt = 0; mt < 2; mt++) {
#pragma unroll
        for (int hf = 0; hf < 2; hf++) {
            int m = m0 + wm * 32 + mt * 16 + hf * 8 + g;
            if (MODE == 0) {
                int b = m >> 11, s = m & 2047;
#pragma unroll
                for (int nt = 0; nt < 8; nt++) {
                    int cl = wn * 64 + nt * 8 + tig * 2;
                    int col = n0 + cl;
                    float e0 = d[mt][nt][hf * 2 + 0] + bias_s[cl];
                    float e1 = d[mt][nt][hf * 2 + 1] + bias_s[cl + 1];
                    uint32_t h01 = pack_bf16x2(e0, e1);
                    float f0 = __uint_as_float(h01 << 16);
                    float f1 = __uint_as_float(h01 & 0xffff0000u);
                    uint32_t l01 = pack_bf16x2(e0 - f0, e1 - f1);
                    int region = col >> 9;
                    int head = (col >> 6) & 7;
                    int d0 = col & 63;
                    if (region == 0) {
                        size_t off = ((size_t)(b * NH + head) * Sdim + s) * HD + d0;
                        *(uint32_t*)&g_q_hi[off] = h01;
                        *(uint32_t*)&g_q_lo[off] = l01;
                    } else if (region == 1) {
                        size_t off = ((size_t)(b * NH + head) * Sdim + s) * HD + d0;
                        *(uint32_t*)&g_k_hi[off] = h01;
                        *(uint32_t*)&g_k_lo[off] = l01;
                    } else {
                        size_t off = ((size_t)b * Sdim + s) * Hdim + (col - 1024);
                        *(uint32_t*)&g_v_hi[off] = h01;
                        *(uint32_t*)&g_v_lo[off] = l01;
                    }
                }
            } else {
                float* crow = Cout + (size_t)m * Ncols;
#pragma unroll
                for (int nt = 0; nt < 8; nt++) {
                    int cl = wn * 64 + nt * 8 + tig * 2;
                    float2 o = {d[mt][nt][hf * 2 + 0] + bias_s[cl],
                                d[mt][nt][hf * 2 + 1] + bias_s[cl + 1]};
                    *(float2*)&crow[n0 + cl] = o;
                }
            }
        }
    }
}

// ---------------------------------------------------------------------------
// K2: scores via mma.sync bf16 (3-term). Epilogue: e = exp2(C*(qk-d2))*maskflag,
// write bf16 hi/lo planes + per-CTA partial row sums. pos+mask packed float4.
// ---------------------------------------------------------------------------
#define SQS 72
#define SC_ARR (128 * SQS)
#define SC_SMEM (4 * SC_ARR * 2 + 2 * 128 * 16 + 128 * 2 * 4)
#define CLOG2E 0.1803368801111137f   // 0.125 * log2(e)

__global__ void __launch_bounds__(256, 2) scores_mma_kernel(
    const float* __restrict__ pos, const int* __restrict__ mask)
{
    extern __shared__ __align__(16) char sm[];
    __nv_bfloat16* Qh = (__nv_bfloat16*)sm;
    float4* Pq4 = (float4*)(sm + 4 * SC_ARR * 2);
    float4* Pk4 = Pq4 + 128;
    float* spart = (float*)(Pk4 + 128);

    const int tid = threadIdx.x, lane = tid & 31, wid = tid >> 5;
    const int bh = blockIdx.z, b = bh >> 3;
    const int q0 = blockIdx.y * 128, k0 = blockIdx.x * 128;
    const int kt = blockIdx.x;

    const __nv_bfloat16* sQh = g_q_hi + ((size_t)bh * Sdim + q0) * HD;
    const __nv_bfloat16* sQl = g_q_lo + ((size_t)bh * Sdim + q0) * HD;
    const __nv_bfloat16* sKh = g_k_hi + ((size_t)bh * Sdim + k0) * HD;
    const __nv_bfloat16* sKl = g_k_lo + ((size_t)bh * Sdim + k0) * HD;

    const uint32_t qb = smem_u32(Qh);
#pragma unroll
    for (int i = 0; i < 4; i++) {
        int idx = tid + 256 * i;
        int r = idx >> 3, c = idx & 7;
        uint32_t so = (r * SQS + c * 8) * 2;
        size_t go = (size_t)r * HD + c * 8;
        cp_async16(qb + so,                  &sQh[go]);
        cp_async16(qb + so + SC_ARR * 2,     &sQl[go]);
        cp_async16(qb + so + 2 * SC_ARR * 2, &sKh[go]);
        cp_async16(qb + so + 3 * SC_ARR * 2, &sKl[go]);
    }
    CP_COMMIT();

    if (tid < 128) {
        const float* pp = &pos[(size_t)(b * Sdim + q0 + tid) * 3];
        Pq4[tid] = make_float4(pp[0], pp[1], pp[2], 0.f);
    } else {
        int t2 = tid - 128;
        const float* pp = &pos[(size_t)(b * Sdim + k0 + t2) * 3];
        float mk = (mask[b * Sdim + k0 + t2] == 0) ? 0.f : 1.f;
        Pk4[t2] = make_float4(pp[0], pp[1], pp[2], mk);
    }
    CP_WAIT0();
    __syncthreads();

    const int wm = wid & 3, wn = wid >> 2;
    const uint32_t kb = qb + 2 * SC_ARR * 2;
    const uint32_t LOFF = SC_ARR * 2;

    float d[2][8][4];
#pragma unroll
    for (int mt = 0; mt < 2; mt++)
#pragma unroll
        for (int nt = 0; nt < 8; nt++)
#pragma unroll
            for (int e = 0; e < 4; e++) d[mt][nt][e] = 0.f;

#pragma unroll
    for (int ks = 0; ks < 4; ks++) {
        uint32_t ah[2][4], al[2][4];
#pragma unroll
        for (int mt = 0; mt < 2; mt++) {
            int row = wm * 32 + mt * 16 + (lane & 15);
            int col = ks * 16 + (lane >> 4) * 8;
            uint32_t adr = qb + (row * SQS + col) * 2;
            ldsm_x4(ah[mt], adr);
            ldsm_x4(al[mt], adr + LOFF);
        }
        uint32_t bhf[8][2], blf[8][2];
#pragma unroll
        for (int nt = 0; nt < 8; nt++) {
            int row = wn * 64 + nt * 8 + (lane & 7);
            int col = ks * 16 + ((lane >> 3) & 1) * 8;
            uint32_t adr = kb + (row * SQS + col) * 2;
            ldsm_x2(bhf[nt], adr);
            ldsm_x2(blf[nt], adr + LOFF);
        }
#pragma unroll
        for (int mt = 0; mt < 2; mt++)
#pragma unroll
            for (int nt = 0; nt < 8; nt++)
                mma_bf16(d[mt][nt], ah[mt], bhf[nt]);
#pragma unroll
        for (int mt = 0; mt < 2; mt++)
#pragma unroll
            for (int nt = 0; nt < 8; nt++)
                mma_bf16(d[mt][nt], ah[mt], blf[nt]);
#pragma unroll
        for (int mt = 0; mt < 2; mt++)
#pragma unroll
            for (int nt = 0; nt < 8; nt++)
                mma_bf16(d[mt][nt], al[mt], bhf[nt]);
    }

    const int g = lane >> 2, tig = lane & 3;
#pragma unroll
    for (int mt = 0; mt < 2; mt++) {
#pragma unroll
        for (int hf = 0; hf < 2; hf++) {
            int lr = wm * 32 + mt * 16 + hf * 8 + g;
            float4 pq = Pq4[lr];
            uint32_t* hrow = g_e_hi + ((size_t)bh * Sdim + q0 + lr) * (Sdim / 2) + (k0 >> 1);
            uint32_t* lrow = g_e_lo + ((size_t)bh * Sdim + q0 + lr) * (Sdim / 2) + (k0 >> 1);
            float rsum = 0.f;
#pragma unroll
            for (int nt = 0; nt < 8; nt++) {
                int lc = wn * 64 + nt * 8 + tig * 2;
                float4 pk0 = Pk4[lc];
                float4 pk1 = Pk4[lc + 1];
                float v0 = d[mt][nt][hf * 2 + 0];
                float v1 = d[mt][nt][hf * 2 + 1];
                float dx0 = pq.x - pk0.x, dy0 = pq.y - pk0.y, dz0 = pq.z - pk0.z;
                float dx1 = pq.x - pk1.x, dy1 = pq.y - pk1.y, dz1 = pq.z - pk1.z;
                float s0 = (v0 - (dx0 * dx0 + dy0 * dy0 + dz0 * dz0)) * CLOG2E;
                float s1 = (v1 - (dx1 * dx1 + dy1 * dy1 + dz1 * dz1)) * CLOG2E;
                float e0 = exp2f(s0) * pk0.w;
                float e1 = exp2f(s1) * pk1.w;
                rsum += e0 + e1;
                uint32_t h01 = pack_bf16x2(e0, e1);
                float f0 = __uint_as_float(h01 << 16);
                float f1 = __uint_as_float(h01 & 0xffff0000u);
                uint32_t l01 = pack_bf16x2(e0 - f0, e1 - f1);
                hrow[lc >> 1] = h01;
                lrow[lc >> 1] = l01;
            }
            rsum += __shfl_xor_sync(0xffffffffu, rsum, 1);
            rsum += __shfl_xor_sync(0xffffffffu, rsum, 2);
            if (tig == 0) spart[lr * 2 + wn] = rsum;
        }
    }
    __syncthreads();
    if (tid < 128) {
        float ps = spart[tid * 2] + spart[tid * 2 + 1];
        g_psum[((size_t)bh * Sdim + q0 + tid) * 16 + kt] = ps;
    }
}

// ---------------------------------------------------------------------------
// K2b: inv = 1 / sum(16 partials)
// ---------------------------------------------------------------------------
__global__ void __launch_bounds__(256) rowsum_inv_kernel()
{
    int idx = blockIdx.x * 256 + threadIdx.x;
    const float* p = g_psum + (size_t)idx * 16;
    float s = 0.f;
#pragma unroll
    for (int i = 0; i < 16; i++) s += p[i];
    g_inv[idx] = 1.0f / s;
}

// ---------------------------------------------------------------------------
// K3: head-mean (pure stream) from hi/lo planes
// ---------------------------------------------------------------------------
__global__ void __launch_bounds__(256) mean_kernel(float* __restrict__ mean_out)
{
    const int bq = blockIdx.x;
    const int b = bq >> 11, q = bq & 2047;
    const int tid = threadIdx.x;
    const int pbase = tid * 4;

    __shared__ float inv_s[8];
    if (tid < 8) inv_s[tid] = g_inv[(size_t)(b * NH + tid) * Sdim + q];
    __syncthreads();

    float macc[8];
#pragma unroll
    for (int j = 0; j < 8; j++) macc[j] = 0.f;

#pragma unroll
    for (int h = 0; h < NH; h++) {
        size_t rb = ((size_t)((b * NH + h) * Sdim + q)) * (Sdim / 2);
        uint4 vh = *(const uint4*)&g_e_hi[rb + pbase];
        uint4 vl = *(const uint4*)&g_e_lo[rb + pbase];
        uint32_t hw[4] = {vh.x, vh.y, vh.z, vh.w};
        uint32_t lw[4] = {vl.x, vl.y, vl.z, vl.w};
        float invh = inv_s[h];
#pragma unroll
        for (int m = 0; m < 4; m++) {
            float e0 = __uint_as_float(hw[m] << 16) + __uint_as_float(lw[m] << 16);
            float e1 = __uint_as_float(hw[m] & 0xffff0000u) + __uint_as_float(lw[m] & 0xffff0000u);
            macc[2 * m]     = fmaf(e0, invh, macc[2 * m]);
            macc[2 * m + 1] = fmaf(e1, invh, macc[2 * m + 1]);
        }
    }

    float* mrow = mean_out + ((size_t)(b * Sdim + q)) * Sdim + tid * 8;
    float4 m0 = {macc[0] * 0.125f, macc[1] * 0.125f, macc[2] * 0.125f, macc[3] * 0.125f};
    float4 m1 = {macc[4] * 0.125f, macc[5] * 0.125f, macc[6] * 0.125f, macc[7] * 0.125f};
    *(float4*)&mrow[0] = m0;
    *(float4*)&mrow[4] = m1;
}

// ---------------------------------------------------------------------------
// K4: pv via mma.sync bf16 (3-term). All operands via cp.async,
// single __syncthreads per chunk. ctx written pre-split bf16 hi/lo.
// ---------------------------------------------------------------------------
#define PV_STAGE_B 49152
#define PV_WL_OFF  16384
#define PV_VH_OFF  32768
#define PV_VL_OFF  40960
#define PV_BASE    1024
#define PV_SMEM_B  (PV_BASE + 2 * PV_STAGE_B)

__global__ void __launch_bounds__(256, 2) pv_mma_kernel()
{
    extern __shared__ __align__(16) char sm[];
    float* inv_s = (float*)sm;

    const int tid = threadIdx.x, lane = tid & 31, wid = tid >> 5;
    const int bh = blockIdx.y, b = bh >> 3, h = bh & 7;
    const int q0 = blockIdx.x * 128;

    const uint32_t* Eh = g_e_hi + ((size_t)bh * Sdim + q0) * (Sdim / 2);
    const uint32_t* El = g_e_lo + ((size_t)bh * Sdim + q0) * (Sdim / 2);
    const __nv_bfloat16* Vh_src = g_v_hi + (size_t)b * Sdim * Hdim + h * HD;
    const __nv_bfloat16* Vl_src = g_v_lo + (size_t)b * Sdim * Hdim + h * HD;

    const uint32_t sb = smem_u32(sm);
    const int wm = wid & 3, wn = wid >> 2;

    if (tid < 128)
        inv_s[tid] = g_inv[(size_t)bh * Sdim + q0 + tid];

    float d[2][4][4];
#pragma unroll
    for (int mt = 0; mt < 2; mt++)
#pragma unroll
        for (int nt = 0; nt < 4; nt++)
#pragma unroll
            for (int e = 0; e < 4; e++) d[mt][nt][e] = 0.f;

#define PV_CPW(kc, st)                                                            \
    _Pragma("unroll") for (int i = 0; i < 4; i++) {                               \
        int idx = tid + 256 * i; int r = idx >> 3, cc = idx & 7;                  \
        uint32_t soff = r * 128 + ((cc * 16) ^ ((r & 7) * 16));                   \
        uint32_t base = sb + PV_BASE + (st) * PV_STAGE_B;                         \
        size_t go = (size_t)r * (Sdim / 2) + ((kc) >> 1) + cc * 4;                \
        cp_async16(base + soff,             &Eh[go]);                             \
        cp_async16(base + PV_WL_OFF + soff, &El[go]);                             \
    }

#define PV_CPV(kc, st)                                                            \
    _Pragma("unroll") for (int i = 0; i < 2; i++) {                               \
        int idx = tid + 256 * i; int kk = idx >> 3, c8 = idx & 7;                 \
        uint32_t soff = kk * 128 + ((c8 * 16) ^ ((kk & 7) * 16));                 \
        uint32_t base = sb + PV_BASE + (st) * PV_STAGE_B;                         \
        cp_async16(base + PV_VH_OFF + soff, &Vh_src[(size_t)((kc) + kk) * Hdim + c8 * 8]); \
        cp_async16(base + PV_VL_OFF + soff, &Vl_src[(size_t)((kc) + kk) * Hdim + c8 * 8]); \
    }

    PV_CPW(0, 0)
    PV_CPV(0, 0)
    CP_COMMIT();
    CP_WAIT0();
    __syncthreads();

    for (int c = 0; c < 32; c++) {
        const int st = c & 1;
        if (c < 31) {
            PV_CPW((c + 1) * 64, st ^ 1)
            PV_CPV((c + 1) * 64, st ^ 1)
            CP_COMMIT();
        }
        {
            const uint32_t wbase = sb + PV_BASE + st * PV_STAGE_B;
            const uint32_t vbase = wbase + PV_VH_OFF;
#pragma unroll
            for (int ks = 0; ks < 4; ks++) {
                uint32_t ah[2][4], al[2][4];
#pragma unroll
                for (int mt = 0; mt < 2; mt++) {
                    int row = wm * 32 + mt * 16 + (lane & 15);
                    uint32_t colb = (ks * 16 + (lane >> 4) * 8) * 2;
                    uint32_t adr = wbase + row * 128 + (colb ^ ((row & 7) * 16));
                    ldsm_x4(ah[mt], adr);
                    ldsm_x4(al[mt], adr + PV_WL_OFF);
                }
                uint32_t bhf[4][2], blf[4][2];
#pragma unroll
                for (int nt = 0; nt < 4; nt++) {
                    int rowk = ks * 16 + (lane & 15);
                    uint32_t colb = (wn * 32 + nt * 8) * 2;
                    uint32_t adr = vbase + rowk * 128 + (colb ^ ((rowk & 7) * 16));
                    ldsm_x2t(bhf[nt], adr);
                    ldsm_x2t(blf[nt], adr + (PV_VL_OFF - PV_VH_OFF));
                }
#pragma unroll
                for (int mt = 0; mt < 2; mt++)
#pragma unroll
                    for (int nt = 0; nt < 4; nt++)
                        mma_bf16(d[mt][nt], ah[mt], bhf[nt]);
#pragma unroll
                for (int mt = 0; mt < 2; mt++)
#pragma unroll
                    for (int nt = 0; nt < 4; nt++)
                        mma_bf16(d[mt][nt], ah[mt], blf[nt]);
#pragma unroll
                for (int mt = 0; mt < 2; mt++)
#pragma unroll
                    for (int nt = 0; nt < 4; nt++)
                        mma_bf16(d[mt][nt], al[mt], bhf[nt]);
            }
        }
        if (c < 31) { CP_WAIT0(); }
        __syncthreads();
    }

    const int g = lane >> 2, tig = lane & 3;
#pragma unroll
    for (int mt = 0; mt < 2; mt++)
#pragma unroll
        for (int nt = 0; nt < 4; nt++)
#pragma unroll
            for (int hf = 0; hf < 2; hf++) {
                int lr = wm * 32 + mt * 16 + g + hf * 8;
                float inv = inv_s[lr];
                int m = q0 + lr;
                int col = h * HD + wn * 32 + nt * 8 + tig * 2;
                float e0 = d[mt][nt][hf * 2 + 0] * inv;
                float e1 = d[mt][nt][hf * 2 + 1] * inv;
                uint32_t h01 = pack_bf16x2(e0, e1);
                float f0 = __uint_as_float(h01 << 16);
                float f1 = __uint_as_float(h01 & 0xffff0000u);
                uint32_t l01 = pack_bf16x2(e0 - f0, e1 - f1);
                size_t off = (size_t)(b * Sdim + m) * Hdim + col;
                *(uint32_t*)&g_ctx_hi[off] = h01;
                *(uint32_t*)&g_ctx_lo[off] = l01;
            }
}

// ---------------------------------------------------------------------------
extern "C" void kernel_launch(void* const* d_in, const int* in_sizes, int n_in,
                              void* d_out, int out_size)
{
    const float* x     = (const float*)d_in[0];
    const float* pos   = (const float*)d_in[1];
    const int*   mask  = (const int*)d_in[2];
    const float* w_qkv = (const float*)d_in[3];
    const float* b_qkv = (const float*)d_in[4];
    const float* w_out = (const float*)d_in[5];
    const float* b_out = (const float*)d_in[6];

    float* out_proj = (float*)d_out;
    float* mean_out = out_proj + (size_t)Bdim * Sdim * Hdim;

    __nv_bfloat16 *p_xh, *p_xl, *p_wqh, *p_wql, *p_woh, *p_wol, *p_ch, *p_cl;
    cudaGetSymbolAddress((void**)&p_xh, g_x_hi);
    cudaGetSymbolAddress((void**)&p_xl, g_x_lo);
    cudaGetSymbolAddress((void**)&p_wqh, g_wqkv_hi);
    cudaGetSymbolAddress((void**)&p_wql, g_wqkv_lo);
    cudaGetSymbolAddress((void**)&p_woh, g_wout_hi);
    cudaGetSymbolAddress((void**)&p_wol, g_wout_lo);
    cudaGetSymbolAddress((void**)&p_ch, g_ctx_hi);
    cudaGetSymbolAddress((void**)&p_cl, g_ctx_lo);

    static cudaStream_t s_side = nullptr;
    static cudaEvent_t ev_fork = nullptr, ev_join = nullptr;
    if (!s_side) {
        cudaStreamCreateWithFlags(&s_side, cudaStreamNonBlocking);
        cudaEventCreateWithFlags(&ev_fork, cudaEventDisableTiming);
        cudaEventCreateWithFlags(&ev_join, cudaEventDisableTiming);
        cudaFuncSetAttribute(gemm512_mma_kernel<0>, cudaFuncAttributeMaxDynamicSharedMemorySize, GQ_SMEM);
        cudaFuncSetAttribute(gemm512_mma_kernel<1>, cudaFuncAttributeMaxDynamicSharedMemorySize, GQ_SMEM);
        cudaFuncSetAttribute(scores_mma_kernel, cudaFuncAttributeMaxDynamicSharedMemorySize, SC_SMEM);
        cudaFuncSetAttribute(pv_mma_kernel, cudaFuncAttributeMaxDynamicSharedMemorySize, PV_SMEM_B);
    }

    // K0: pre-split fp32 inputs to bf16 hi/lo
    split4_kernel<<<(Bdim * Sdim * Hdim / 4 + 255) / 256, 256>>>(x, p_xh, p_xl, Bdim * Sdim * Hdim / 4);
    split4_kernel<<<(H3 * Hdim / 4 + 255) / 256, 256>>>(w_qkv, p_wqh, p_wql, H3 * Hdim / 4);
    split4_kernel<<<(Hdim * Hdim / 4 + 255) / 256, 256>>>(w_out, p_woh, p_wol, Hdim * Hdim / 4);

    // K1: QKV projection (tensor) + split scatter
    {
        dim3 grid(H3 / 128, (Bdim * Sdim) / 128);
        gemm512_mma_kernel<0><<<grid, 256, GQ_SMEM>>>(p_xh, p_xl, p_wqh, p_wql, b_qkv, nullptr, H3);
    }
    // K2: scores -> exp hi/lo planes + partial sums
    {
        dim3 grid(Sdim / 128, Sdim / 128, Bdim * NH);
        scores_mma_kernel<<<grid, 256, SC_SMEM>>>(pos, mask);
    }
    // K2b: row inverse sums
    rowsum_inv_kernel<<<(Bdim * NH * Sdim) / 256, 256>>>();

    // K4: pv gets the memory system to itself
    {
        dim3 grid(Sdim / 128, Bdim * NH);
        pv_mma_kernel<<<grid, 256, PV_SMEM_B>>>();
    }

    // fork: mean (DRAM-bound, side stream) overlaps out-proj (compute-bound, main)
    cudaEventRecord(ev_fork, 0);
    cudaStreamWaitEvent(s_side, ev_fork, 0);
    mean_kernel<<<Bdim * Sdim, 256, 0, s_side>>>(mean_out);
    cudaEventRecord(ev_join, s_side);

    // K5: output projection (tensor)
    {
        dim3 grid(Hdim / 128, (Bdim * Sdim) / 128);
        gemm512_mma_kernel<1><<<grid, 256, GQ_SMEM>>>(p_ch, p_cl, p_woh, p_wol, b_out, out_proj, Hdim);
    }
    // join
    cudaStreamWaitEvent(0, ev_join, 0);
}